// round 15
// baseline (speedup 1.0000x reference)
#include <cuda_runtime.h>
#include <cuda_fp16.h>
#include <cstdint>

#define NN_MAX 50000
#define ME_MAX 20000
#define E_MAX  800000

// ---------------- scratch (static device globals; no allocation) ----------------
__device__ float g_Q[NN_MAX * 128];
__device__ __align__(16) __half g_Kh[ME_MAX * 128];
__device__ __align__(16) __half g_Vh[ME_MAX * 128];
__device__ float g_attn[NN_MAX * 128];
__device__ int   g_count[NN_MAX];
__device__ int   g_offset[NN_MAX + 1];
__device__ int   g_cursor[NN_MAX];
__device__ int   g_edge_dst[E_MAX];
// split weights: [which][hi/lo][n*136 + k]  (fp16, transposed to [n][k], row stride 136)
__device__ __align__(16) __half g_Wsp[4][2][128 * 136];

// ---------------- CSR build ----------------
__global__ void k_zero(int n) {
    int i = blockIdx.x * blockDim.x + threadIdx.x;
    if (i < n) g_count[i] = 0;
}

__global__ void k_hist(const int* __restrict__ src, int E) {
    int e = blockIdx.x * blockDim.x + threadIdx.x;
    if (e < E) atomicAdd(&g_count[src[e]], 1);
}

__global__ void k_scan(int n) {
    __shared__ int sm[1024];
    int t = threadIdx.x;
    int chunk = (n + 1023) >> 10;
    int b = t * chunk;
    int e = min(b + chunk, n);
    int s = 0;
    for (int i = b; i < e; i++) s += g_count[i];
    sm[t] = s;
    __syncthreads();
    for (int o = 1; o < 1024; o <<= 1) {
        int v = (t >= o) ? sm[t - o] : 0;
        __syncthreads();
        sm[t] += v;
        __syncthreads();
    }
    int run = (t == 0) ? 0 : sm[t - 1];
    for (int i = b; i < e; i++) {
        int c = g_count[i];
        g_offset[i] = run;
        g_cursor[i] = run;
        run += c;
    }
    if (t == 1023) g_offset[n] = sm[1023];
}

__global__ void k_scatter(const int* __restrict__ src, const int* __restrict__ dst, int E) {
    int e = blockIdx.x * blockDim.x + threadIdx.x;
    if (e < E) {
        int p = atomicAdd(&g_cursor[src[e]], 1);
        g_edge_dst[p] = dst[e];
    }
}

// ---------------- weight split: W[k][n] fp32 -> fp16 hi/lo, transposed [n][k] ----------------
__global__ void k_splitW(const float* __restrict__ W0, const float* __restrict__ W1,
                         const float* __restrict__ W2, const float* __restrict__ W3) {
    int w = blockIdx.y;
    const float* W = (w == 0) ? W0 : (w == 1) ? W1 : (w == 2) ? W2 : W3;
    int gid = blockIdx.x * 256 + threadIdx.x;   // 0..16383
    int n = gid >> 7;
    int k = gid & 127;
    float x = W[k * 128 + n];
    __half h = __float2half_rn(x);
    __half l = __float2half_rn(x - __half2float(h));
    g_Wsp[w][0][n * 136 + k] = h;
    g_Wsp[w][1][n * 136 + k] = l;
}

// ---------------- fp16 2-term tensor-core GEMM, 64x64 tiles for occupancy ----------------
// C[M, 64-col half] = fp16(A[M,128]) @ (Wh + Wl) + bias (+R).
// MODE 0: fp32 out.  MODE 1: fp16 out.  MODE 2: fp32 out + resid.
// grid = (ceil(M/64), 2): blockIdx.y selects the N-half.  52 KB smem -> 4 CTAs/SM.
// 256 thr = 8 warps (2m x 4n), warp tile 32x16, per warp per kk: 2 A-ldsm + 2 B-ldsm, 8 MMAs.

__device__ __forceinline__ void mma_fp16(float* c, const uint32_t* a, const uint32_t* b) {
    asm volatile(
        "mma.sync.aligned.m16n8k16.row.col.f32.f16.f16.f32 "
        "{%0,%1,%2,%3}, {%4,%5,%6,%7}, {%8,%9}, {%0,%1,%2,%3};"
        : "+f"(c[0]), "+f"(c[1]), "+f"(c[2]), "+f"(c[3])
        : "r"(a[0]), "r"(a[1]), "r"(a[2]), "r"(a[3]), "r"(b[0]), "r"(b[1]));
}

__device__ __forceinline__ void ldsm4(uint32_t& r0, uint32_t& r1, uint32_t& r2, uint32_t& r3,
                                      uint32_t addr) {
    asm volatile("ldmatrix.sync.aligned.m8n8.x4.shared.b16 {%0,%1,%2,%3}, [%4];"
                 : "=r"(r0), "=r"(r1), "=r"(r2), "=r"(r3) : "r"(addr));
}

#define WS 68   // row stride in b32 units (136 fp16, 272 bytes)
#define ROWB (WS * 4)                       // 272 bytes per row
#define GEMM_SMEM ((3 * 64 * WS) * 4)       // Wh(64) + Wl(64) + A(64) rows = 52224 bytes
#define LO_W (64 * WS * 4)                  // byte offset Wh -> Wl (within CTA's half)
#define W_ROW_U4 17                         // uint4 per W row (272/16)

template <int MODE>
__global__ __launch_bounds__(256, 4) void k_gemmB(
    const float* __restrict__ A, const uint4* __restrict__ Wsp,
    const float* __restrict__ bias, const float* __restrict__ R,
    void* __restrict__ Cout, int M)
{
    extern __shared__ uint32_t sm[];
    uint32_t* sW = sm;                 // 64 rows hi, then 64 rows lo
    uint32_t* sA = sm + 2 * 64 * WS;   // 64 rows fp16

    const int t = threadIdx.x;
    const int lane = t & 31, warp = t >> 5;
    const int l4 = lane & 3, l28 = lane >> 2;
    const int wm = warp >> 2;   // 0..1  (x32 rows)
    const int wn = warp & 3;    // 0..3  (x16 cols)
    const int row0 = blockIdx.x * 64;
    const int col0 = blockIdx.y * 64;

    // stage W half: hi rows [col0, col0+64) then lo rows, 1088 uint4 each
    {
        uint4* dW = (uint4*)sW;
        const uint4* sHi = Wsp + (size_t)col0 * W_ROW_U4;
        const uint4* sLo = Wsp + (size_t)(128 + col0) * W_ROW_U4;
#pragma unroll
        for (int i = 0; i < 5; i++) {
            int idx = t + i * 256;
            if (idx < 1088) {
                dW[idx] = sHi[idx];
                dW[idx + 1088] = sLo[idx];
            }
        }
    }
    // stage A: 64 rows x 128 cols fp32 -> fp16.  4 threads/row, 8 float4 each.
    {
        int m = t >> 2;
        int q = t & 3;
        int arow = row0 + m;
        if (arow >= M) arow = M - 1;
        const float4* Ap = (const float4*)(A + (size_t)arow * 128);
#pragma unroll
        for (int i = 0; i < 8; i++) {
            int col = q * 32 + i * 4;
            float4 v = Ap[col >> 2];
            __half2 h01 = __floats2half2_rn(v.x, v.y);
            __half2 h23 = __floats2half2_rn(v.z, v.w);
            int o = m * WS + (col >> 1);
            sA[o]     = *(uint32_t*)&h01;
            sA[o + 1] = *(uint32_t*)&h23;
        }
    }
    __syncthreads();

    float c[2][2][4];
#pragma unroll
    for (int mi = 0; mi < 2; mi++)
#pragma unroll
        for (int ni = 0; ni < 2; ni++)
#pragma unroll
            for (int r = 0; r < 4; r++) c[mi][ni][r] = 0.0f;

    uint32_t aAddr[2], bAddr;
    {
        uint32_t baseA = (uint32_t)__cvta_generic_to_shared(sA);
        uint32_t baseW = (uint32_t)__cvta_generic_to_shared(sW);
        int am = wm * 32 + (lane & 15);
        int ac = lane >> 4;                       // k chunk
#pragma unroll
        for (int mi = 0; mi < 2; mi++)
            aAddr[mi] = baseA + (am + mi * 16) * ROWB + ac * 16;
        int bn = (lane & 7) + ((lane >> 4) << 3); // n within warp's 16
        int bc = (lane >> 3) & 1;                 // k chunk
        bAddr = baseW + (wn * 16 + bn) * ROWB + bc * 16;
    }

#pragma unroll
    for (int kk = 0; kk < 8; kk++) {
        uint32_t ah[2][4], bh[4], bl[4];
#pragma unroll
        for (int mi = 0; mi < 2; mi++) {
            uint32_t ad = aAddr[mi] + kk * 32;
            ldsm4(ah[mi][0], ah[mi][1], ah[mi][2], ah[mi][3], ad);
        }
        {
            uint32_t bd = bAddr + kk * 32;
            ldsm4(bh[0], bh[1], bh[2], bh[3], bd);
            ldsm4(bl[0], bl[1], bl[2], bl[3], bd + LO_W);
        }
#pragma unroll
        for (int mi = 0; mi < 2; mi++)
#pragma unroll
            for (int ni = 0; ni < 2; ni++) {
                mma_fp16(c[mi][ni], ah[mi], &bh[ni * 2]);
                mma_fp16(c[mi][ni], ah[mi], &bl[ni * 2]);
            }
    }

    // epilogue: c0=(r,2c), c1=(r,2c+1), c2=(r+8,2c), c3=(r+8,2c+1)
#pragma unroll
    for (int mi = 0; mi < 2; mi++) {
#pragma unroll
        for (int ni = 0; ni < 2; ni++) {
            int gr = row0 + wm * 32 + mi * 16 + l28;
            int gc = col0 + wn * 16 + ni * 8 + 2 * l4;
            float b0 = bias[gc], b1 = bias[gc + 1];
            if (gr < M) {
                float ox = c[mi][ni][0] + b0;
                float oy = c[mi][ni][1] + b1;
                if (MODE == 2) {
                    float2 r = *(const float2*)(R + (size_t)gr * 128 + gc);
                    ox += r.x; oy += r.y;
                }
                if (MODE == 1) {
                    ((__half2*)Cout)[(size_t)gr * 64 + (gc >> 1)] = __floats2half2_rn(ox, oy);
                } else {
                    *(float2*)((float*)Cout + (size_t)gr * 128 + gc) = make_float2(ox, oy);
                }
            }
            if (gr + 8 < M) {
                float ox = c[mi][ni][2] + b0;
                float oy = c[mi][ni][3] + b1;
                if (MODE == 2) {
                    float2 r = *(const float2*)(R + (size_t)(gr + 8) * 128 + gc);
                    ox += r.x; oy += r.y;
                }
                if (MODE == 1) {
                    ((__half2*)Cout)[(size_t)(gr + 8) * 64 + (gc >> 1)] = __floats2half2_rn(ox, oy);
                } else {
                    *(float2*)((float*)Cout + (size_t)(gr + 8) * 128 + gc) = make_float2(ox, oy);
                }
            }
        }
    }
}

// ---------------- fused per-node attention (one warp per node, 4-edge unroll, fp16 K/V) ----------------
__device__ __forceinline__ float dot_kh(const float4& q, uint2 u) {
    float2 a = __half22float2(*(__half2*)&u.x);
    float2 b = __half22float2(*(__half2*)&u.y);
    return q.x * a.x + q.y * a.y + q.z * b.x + q.w * b.y;
}

__global__ __launch_bounds__(256) void k_attn(int NN) {
    int warp = threadIdx.x >> 5;
    int lane = threadIdx.x & 31;
    int n = blockIdx.x * 8 + warp;
    if (n >= NN) return;

    const float4* Q4 = (const float4*)g_Q;
    const uint2* K2 = (const uint2*)g_Kh;   // row = 32 uint2 (128 halves)
    const uint2* V2 = (const uint2*)g_Vh;

    float4 q = Q4[(size_t)n * 32 + lane];   // lane holds dims [lane*4, lane*4+4); head = lane/8
    float z = 0.0f;
    float ax = 0.0f, ay = 0.0f, az = 0.0f, aw = 0.0f;
    const float sc = 0.17677669529663687f;  // 1/sqrt(32)

    int beg = g_offset[n];
    int end = g_offset[n + 1];
    int j = beg;
    for (; j + 4 <= end; j += 4) {
        int d0 = g_edge_dst[j + 0];
        int d1 = g_edge_dst[j + 1];
        int d2 = g_edge_dst[j + 2];
        int d3 = g_edge_dst[j + 3];
        uint2 k0 = K2[(size_t)d0 * 32 + lane];
        uint2 k1 = K2[(size_t)d1 * 32 + lane];
        uint2 k2 = K2[(size_t)d2 * 32 + lane];
        uint2 k3 = K2[(size_t)d3 * 32 + lane];
        uint2 v0 = V2[(size_t)d0 * 32 + lane];
        uint2 v1 = V2[(size_t)d1 * 32 + lane];
        uint2 v2 = V2[(size_t)d2 * 32 + lane];
        uint2 v3 = V2[(size_t)d3 * 32 + lane];

        float p0 = dot_kh(q, k0);
        float p1 = dot_kh(q, k1);
        float p2 = dot_kh(q, k2);
        float p3 = dot_kh(q, k3);
#pragma unroll
        for (int o = 1; o <= 4; o <<= 1) {
            p0 += __shfl_xor_sync(0xffffffffu, p0, o);
            p1 += __shfl_xor_sync(0xffffffffu, p1, o);
            p2 += __shfl_xor_sync(0xffffffffu, p2, o);
            p3 += __shfl_xor_sync(0xffffffffu, p3, o);
        }
        float e0 = __expf(p0 * sc);
        float e1 = __expf(p1 * sc);
        float e2 = __expf(p2 * sc);
        float e3 = __expf(p3 * sc);
        z += (e0 + e1) + (e2 + e3);
        float2 va, vb;
        va = __half22float2(*(__half2*)&v0.x); vb = __half22float2(*(__half2*)&v0.y);
        ax += e0 * va.x; ay += e0 * va.y; az += e0 * vb.x; aw += e0 * vb.y;
        va = __half22float2(*(__half2*)&v1.x); vb = __half22float2(*(__half2*)&v1.y);
        ax += e1 * va.x; ay += e1 * va.y; az += e1 * vb.x; aw += e1 * vb.y;
        va = __half22float2(*(__half2*)&v2.x); vb = __half22float2(*(__half2*)&v2.y);
        ax += e2 * va.x; ay += e2 * va.y; az += e2 * vb.x; aw += e2 * vb.y;
        va = __half22float2(*(__half2*)&v3.x); vb = __half22float2(*(__half2*)&v3.y);
        ax += e3 * va.x; ay += e3 * va.y; az += e3 * vb.x; aw += e3 * vb.y;
    }
    for (; j < end; j++) {
        int d = g_edge_dst[j];
        uint2 ku = K2[(size_t)d * 32 + lane];
        uint2 vu = V2[(size_t)d * 32 + lane];
        float p = dot_kh(q, ku);
        p += __shfl_xor_sync(0xffffffffu, p, 1);
        p += __shfl_xor_sync(0xffffffffu, p, 2);
        p += __shfl_xor_sync(0xffffffffu, p, 4);
        float e = __expf(p * sc);
        z += e;
        float2 va = __half22float2(*(__half2*)&vu.x);
        float2 vb = __half22float2(*(__half2*)&vu.y);
        ax += e * va.x; ay += e * va.y; az += e * vb.x; aw += e * vb.y;
    }
    float inv = (z > 0.0f) ? (1.0f / z) : 0.0f;
    float4 o;
    o.x = ax * inv; o.y = ay * inv; o.z = az * inv; o.w = aw * inv;
    ((float4*)g_attn)[(size_t)n * 32 + lane] = o;
}

// ---------------- launch ----------------
extern "C" void kernel_launch(void* const* d_in, const int* in_sizes, int n_in,
                              void* d_out, int out_size)
{
    const float* x_node = (const float*)d_in[0];
    const float* x_edge = (const float*)d_in[1];
    const int*   src    = (const int*)d_in[2];
    const int*   dst    = (const int*)d_in[3];
    const float* Wq     = (const float*)d_in[4];
    const float* bq     = (const float*)d_in[5];
    const float* Wk     = (const float*)d_in[6];
    const float* bk     = (const float*)d_in[7];
    const float* Wv     = (const float*)d_in[8];
    const float* bv     = (const float*)d_in[9];
    const float* Wo     = (const float*)d_in[10];
    const float* bo     = (const float*)d_in[11];
    float* out = (float*)d_out;

    int NN = in_sizes[0] / 128;
    int ME = in_sizes[1] / 128;
    int E  = in_sizes[2];

    float *Qp, *Ap;
    __half *Khp, *Vhp;
    uint4* Wspp;
    cudaGetSymbolAddress((void**)&Qp, g_Q);
    cudaGetSymbolAddress((void**)&Khp, g_Kh);
    cudaGetSymbolAddress((void**)&Vhp, g_Vh);
    cudaGetSymbolAddress((void**)&Ap, g_attn);
    cudaGetSymbolAddress((void**)&Wspp, g_Wsp);
    const size_t wstride = (size_t)2 * 128 * 136 * sizeof(__half) / sizeof(uint4);

    cudaFuncSetAttribute(k_gemmB<0>, cudaFuncAttributeMaxDynamicSharedMemorySize, GEMM_SMEM);
    cudaFuncSetAttribute(k_gemmB<1>, cudaFuncAttributeMaxDynamicSharedMemorySize, GEMM_SMEM);
    cudaFuncSetAttribute(k_gemmB<2>, cudaFuncAttributeMaxDynamicSharedMemorySize, GEMM_SMEM);

    dim3 gq((NN + 63) / 64, 2);
    dim3 ge((ME + 63) / 64, 2);

    k_zero<<<(NN + 255) / 256, 256>>>(NN);
    k_splitW<<<dim3(64, 4), 256>>>(Wq, Wk, Wv, Wo);
    k_gemmB<0><<<gq, 256, GEMM_SMEM>>>(x_node, Wspp + 0 * wstride, bq, nullptr, Qp, NN);
    k_gemmB<1><<<ge, 256, GEMM_SMEM>>>(x_edge, Wspp + 1 * wstride, bk, nullptr, Khp, ME);
    k_gemmB<1><<<ge, 256, GEMM_SMEM>>>(x_edge, Wspp + 2 * wstride, bv, nullptr, Vhp, ME);
    k_hist<<<(E + 255) / 256, 256>>>(src, E);
    k_scan<<<1, 1024>>>(NN);
    k_scatter<<<(E + 255) / 256, 256>>>(src, dst, E);
    k_attn<<<(NN + 7) / 8, 256>>>(NN);
    k_gemmB<2><<<gq, 256, GEMM_SMEM>>>(Ap, Wspp + 3 * wstride, bo, x_node, out, NN);
}

// round 17
// speedup vs baseline: 1.0504x; 1.0504x over previous
#include <cuda_runtime.h>
#include <cuda_fp16.h>
#include <cstdint>

#define NN_MAX 50000
#define ME_MAX 20000
#define E_MAX  800000

// ---------------- scratch (static device globals; no allocation) ----------------
__device__ float g_Q[NN_MAX * 128];
__device__ __align__(16) __half g_Kh[ME_MAX * 128];
__device__ __align__(16) __half g_Vh[ME_MAX * 128];
__device__ float g_attn[NN_MAX * 128];
__device__ int   g_count[NN_MAX];      // zero-initialized at load; k_scan re-zeroes after reading
__device__ int   g_offset[NN_MAX + 1];
__device__ int   g_cursor[NN_MAX];
__device__ int   g_edge_dst[E_MAX];
// split weights: [which][hi/lo][n*136 + k]  (fp16, transposed to [n][k], row stride 136)
__device__ __align__(16) __half g_Wsp[4][2][128 * 136];

// ---------------- prep: weight split (blocks 0..255) + edge histogram (rest) ----------------
#define HIST_BLKS 192
__global__ void k_prep(const float* __restrict__ W0, const float* __restrict__ W1,
                       const float* __restrict__ W2, const float* __restrict__ W3,
                       const int* __restrict__ src, int E) {
    int b = blockIdx.x;
    int tid = threadIdx.x;
    if (b < 256) {
        int gid = b * 256 + tid;        // 0..65535: 4 matrices x 16384
        int w = gid >> 14;
        int r = gid & 16383;
        int n = r >> 7;
        int k = r & 127;
        const float* W = (w == 0) ? W0 : (w == 1) ? W1 : (w == 2) ? W2 : W3;
        float x = W[k * 128 + n];
        __half h = __float2half_rn(x);
        __half l = __float2half_rn(x - __half2float(h));
        g_Wsp[w][0][n * 136 + k] = h;
        g_Wsp[w][1][n * 136 + k] = l;
    } else {
        int e0 = (b - 256) * 256 + tid;
        const int stride = HIST_BLKS * 256;
        for (int e = e0; e < E; e += stride)
            atomicAdd(&g_count[src[e]], 1);
    }
}

// ---------------- scan: exclusive prefix over g_count -> g_offset/g_cursor; re-zero g_count ----------------
__global__ void k_scan(int n) {
    __shared__ int sm[1024];
    int t = threadIdx.x;
    int chunk = (n + 1023) >> 10;
    int b = t * chunk;
    int e = min(b + chunk, n);
    int s = 0;
    for (int i = b; i < e; i++) s += g_count[i];
    sm[t] = s;
    __syncthreads();
    for (int o = 1; o < 1024; o <<= 1) {
        int v = (t >= o) ? sm[t - o] : 0;
        __syncthreads();
        sm[t] += v;
        __syncthreads();
    }
    int run = (t == 0) ? 0 : sm[t - 1];
    for (int i = b; i < e; i++) {
        int c = g_count[i];
        g_count[i] = 0;                 // restore invariant for the next graph replay
        g_offset[i] = run;
        g_cursor[i] = run;
        run += c;
    }
    if (t == 1023) g_offset[n] = sm[1023];
}

// ---------------- fp16 2-term tensor-core GEMM body (64x128 tile, round-12 config) ----------------
__device__ __forceinline__ void mma_fp16(float* c, const uint32_t* a, const uint32_t* b) {
    asm volatile(
        "mma.sync.aligned.m16n8k16.row.col.f32.f16.f16.f32 "
        "{%0,%1,%2,%3}, {%4,%5,%6,%7}, {%8,%9}, {%0,%1,%2,%3};"
        : "+f"(c[0]), "+f"(c[1]), "+f"(c[2]), "+f"(c[3])
        : "r"(a[0]), "r"(a[1]), "r"(a[2]), "r"(a[3]), "r"(b[0]), "r"(b[1]));
}

__device__ __forceinline__ void ldsm4(uint32_t& r0, uint32_t& r1, uint32_t& r2, uint32_t& r3,
                                      uint32_t addr) {
    asm volatile("ldmatrix.sync.aligned.m8n8.x4.shared.b16 {%0,%1,%2,%3}, [%4];"
                 : "=r"(r0), "=r"(r1), "=r"(r2), "=r"(r3) : "r"(addr));
}

#define WS 68   // row stride in b32 units (136 fp16, 272 bytes)
#define ROWB (WS * 4)
#define GEMM_SMEM ((2 * 128 * WS + 64 * WS) * 4)  // 87040 bytes
#define LO_W (128 * WS * 4)                        // byte offset Wh -> Wl

__device__ __forceinline__ void gemm_body(
    uint32_t* sm, const float* __restrict__ A, const uint4* __restrict__ Wsp,
    const float* __restrict__ bias, void* __restrict__ Cout, int M, int blk,
    bool fp16out, const float* __restrict__ R)
{
    uint32_t* sW = sm;                 // 128 rows hi then 128 rows lo
    uint32_t* sA = sm + 2 * 128 * WS;  // 64 rows fp16

    const int t = threadIdx.x;
    const int lane = t & 31, warp = t >> 5;
    const int l4 = lane & 3, l28 = lane >> 2;
    const int wm = warp & 1;    // x32 rows
    const int wn = warp >> 1;   // x32 cols
    const int row0 = blk * 64;

    // stage W (hi+lo contiguous): 4352 uint4 -> 17/thread
    {
        uint4* dW = (uint4*)sW;
#pragma unroll
        for (int i = 0; i < 17; i++)
            dW[t + i * 256] = Wsp[t + i * 256];
    }
    // stage A: 64 rows x 128 cols fp32 -> fp16.  4 threads/row, 8 float4 each.
    {
        int m = t >> 2;
        int q = t & 3;
        int arow = row0 + m;
        if (arow >= M) arow = M - 1;
        const float4* Ap = (const float4*)(A + (size_t)arow * 128);
#pragma unroll
        for (int i = 0; i < 8; i++) {
            int col = q * 32 + i * 4;
            float4 v = Ap[col >> 2];
            __half2 h01 = __floats2half2_rn(v.x, v.y);
            __half2 h23 = __floats2half2_rn(v.z, v.w);
            int o = m * WS + (col >> 1);
            sA[o]     = *(uint32_t*)&h01;
            sA[o + 1] = *(uint32_t*)&h23;
        }
    }
    __syncthreads();

    float c[2][4][4];
#pragma unroll
    for (int mi = 0; mi < 2; mi++)
#pragma unroll
        for (int ni = 0; ni < 4; ni++)
#pragma unroll
            for (int r = 0; r < 4; r++) c[mi][ni][r] = 0.0f;

    uint32_t aAddr[2], bAddr[2];
    {
        uint32_t baseA = (uint32_t)__cvta_generic_to_shared(sA);
        uint32_t baseW = (uint32_t)__cvta_generic_to_shared(sW);
        int am = wm * 32 + (lane & 15);
        int ac = lane >> 4;
#pragma unroll
        for (int mi = 0; mi < 2; mi++)
            aAddr[mi] = baseA + (am + mi * 16) * ROWB + ac * 16;
        int bn = (lane & 7) + ((lane >> 4) << 3);
        int bc = (lane >> 3) & 1;
#pragma unroll
        for (int p = 0; p < 2; p++)
            bAddr[p] = baseW + (wn * 32 + p * 16 + bn) * ROWB + bc * 16;
    }

#pragma unroll
    for (int kk = 0; kk < 8; kk++) {
        uint32_t ah[2][4], bh[2][4], bl[2][4];
#pragma unroll
        for (int mi = 0; mi < 2; mi++) {
            uint32_t ad = aAddr[mi] + kk * 32;
            ldsm4(ah[mi][0], ah[mi][1], ah[mi][2], ah[mi][3], ad);
        }
#pragma unroll
        for (int p = 0; p < 2; p++) {
            uint32_t bd = bAddr[p] + kk * 32;
            ldsm4(bh[p][0], bh[p][1], bh[p][2], bh[p][3], bd);
            ldsm4(bl[p][0], bl[p][1], bl[p][2], bl[p][3], bd + LO_W);
        }
#pragma unroll
        for (int mi = 0; mi < 2; mi++)
#pragma unroll
            for (int ni = 0; ni < 4; ni++) {
                const uint32_t* pbh = &bh[ni >> 1][(ni & 1) * 2];
                const uint32_t* pbl = &bl[ni >> 1][(ni & 1) * 2];
                mma_fp16(c[mi][ni], ah[mi], pbh);
                mma_fp16(c[mi][ni], ah[mi], pbl);
            }
    }

    // epilogue: c0=(r,2c), c1=(r,2c+1), c2=(r+8,2c), c3=(r+8,2c+1)
#pragma unroll
    for (int mi = 0; mi < 2; mi++) {
#pragma unroll
        for (int ni = 0; ni < 4; ni++) {
            int gr = row0 + wm * 32 + mi * 16 + l28;
            int gc = wn * 32 + ni * 8 + 2 * l4;
            float b0 = bias[gc], b1 = bias[gc + 1];
            if (gr < M) {
                float ox = c[mi][ni][0] + b0;
                float oy = c[mi][ni][1] + b1;
                if (R) {
                    float2 r = *(const float2*)(R + (size_t)gr * 128 + gc);
                    ox += r.x; oy += r.y;
                }
                if (fp16out)
                    ((__half2*)Cout)[(size_t)gr * 64 + (gc >> 1)] = __floats2half2_rn(ox, oy);
                else
                    *(float2*)((float*)Cout + (size_t)gr * 128 + gc) = make_float2(ox, oy);
            }
            if (gr + 8 < M) {
                float ox = c[mi][ni][2] + b0;
                float oy = c[mi][ni][3] + b1;
                if (R) {
                    float2 r = *(const float2*)(R + (size_t)(gr + 8) * 128 + gc);
                    ox += r.x; oy += r.y;
                }
                if (fp16out)
                    ((__half2*)Cout)[(size_t)(gr + 8) * 64 + (gc >> 1)] = __floats2half2_rn(ox, oy);
                else
                    *(float2*)((float*)Cout + (size_t)(gr + 8) * 128 + gc) = make_float2(ox, oy);
            }
        }
    }
}

// ---------------- mega launch: scatter (grid-stride, first) + Q/K/V GEMMs ----------------
#define SCAT_BLKS 128
__global__ __launch_bounds__(256, 2) void k_mega(
    const float* __restrict__ x_node, const float* __restrict__ x_edge,
    const int* __restrict__ src, const int* __restrict__ dst,
    const uint4* __restrict__ Wsp,
    const float* __restrict__ bq, const float* __restrict__ bk, const float* __restrict__ bv,
    float* __restrict__ Qout, __half* __restrict__ Kout, __half* __restrict__ Vout,
    int NN, int ME, int E, int gq, int ge, int wstride)
{
    extern __shared__ uint32_t smem[];
    int b = blockIdx.x;
    if (b < SCAT_BLKS) {
        // scatter: runs concurrently under the GEMM wave
        int e0 = b * 256 + threadIdx.x;
        const int stride = SCAT_BLKS * 256;
        for (int e = e0; e < E; e += stride) {
            int p = atomicAdd(&g_cursor[src[e]], 1);
            g_edge_dst[p] = dst[e];
        }
        return;
    }
    b -= SCAT_BLKS;
    const float* A; const uint4* W; const float* bias; void* out; int M; bool f16; int blk;
    if (b < gq)           { A = x_node; W = Wsp;               bias = bq; out = Qout; M = NN; f16 = false; blk = b; }
    else if (b < gq + ge) { A = x_edge; W = Wsp + wstride;     bias = bk; out = Kout; M = ME; f16 = true;  blk = b - gq; }
    else                  { A = x_edge; W = Wsp + 2 * wstride; bias = bv; out = Vout; M = ME; f16 = true;  blk = b - gq - ge; }
    gemm_body(smem, A, W, bias, out, M, blk, f16, nullptr);
}

// ---------------- O GEMM (fp32 out + bias + residual) ----------------
__global__ __launch_bounds__(256, 2) void k_gemmO(
    const float* __restrict__ A, const uint4* __restrict__ Wsp,
    const float* __restrict__ bias, const float* __restrict__ R,
    float* __restrict__ Cout, int M)
{
    extern __shared__ uint32_t smem[];
    gemm_body(smem, A, Wsp, bias, Cout, M, blockIdx.x, false, R);
}

// ---------------- fused per-node attention (one warp per node, 4-edge unroll, fp16 K/V) ----------------
__device__ __forceinline__ float dot_kh(const float4& q, uint2 u) {
    float2 a = __half22float2(*(__half2*)&u.x);
    float2 b = __half22float2(*(__half2*)&u.y);
    return q.x * a.x + q.y * a.y + q.z * b.x + q.w * b.y;
}

__global__ __launch_bounds__(256) void k_attn(int NN) {
    int warp = threadIdx.x >> 5;
    int lane = threadIdx.x & 31;
    int n = blockIdx.x * 8 + warp;
    if (n >= NN) return;

    const float4* Q4 = (const float4*)g_Q;
    const uint2* K2 = (const uint2*)g_Kh;
    const uint2* V2 = (const uint2*)g_Vh;

    float4 q = Q4[(size_t)n * 32 + lane];
    float z = 0.0f;
    float ax = 0.0f, ay = 0.0f, az = 0.0f, aw = 0.0f;
    const float sc = 0.17677669529663687f;  // 1/sqrt(32)

    int beg = g_offset[n];
    int end = g_offset[n + 1];
    int j = beg;
    for (; j + 4 <= end; j += 4) {
        int d0 = g_edge_dst[j + 0];
        int d1 = g_edge_dst[j + 1];
        int d2 = g_edge_dst[j + 2];
        int d3 = g_edge_dst[j + 3];
        uint2 k0 = K2[(size_t)d0 * 32 + lane];
        uint2 k1 = K2[(size_t)d1 * 32 + lane];
        uint2 k2 = K2[(size_t)d2 * 32 + lane];
        uint2 k3 = K2[(size_t)d3 * 32 + lane];
        uint2 v0 = V2[(size_t)d0 * 32 + lane];
        uint2 v1 = V2[(size_t)d1 * 32 + lane];
        uint2 v2 = V2[(size_t)d2 * 32 + lane];
        uint2 v3 = V2[(size_t)d3 * 32 + lane];

        float p0 = dot_kh(q, k0);
        float p1 = dot_kh(q, k1);
        float p2 = dot_kh(q, k2);
        float p3 = dot_kh(q, k3);
#pragma unroll
        for (int o = 1; o <= 4; o <<= 1) {
            p0 += __shfl_xor_sync(0xffffffffu, p0, o);
            p1 += __shfl_xor_sync(0xffffffffu, p1, o);
            p2 += __shfl_xor_sync(0xffffffffu, p2, o);
            p3 += __shfl_xor_sync(0xffffffffu, p3, o);
        }
        float e0 = __expf(p0 * sc);
        float e1 = __expf(p1 * sc);
        float e2 = __expf(p2 * sc);
        float e3 = __expf(p3 * sc);
        z += (e0 + e1) + (e2 + e3);
        float2 va, vb;
        va = __half22float2(*(__half2*)&v0.x); vb = __half22float2(*(__half2*)&v0.y);
        ax += e0 * va.x; ay += e0 * va.y; az += e0 * vb.x; aw += e0 * vb.y;
        va = __half22float2(*(__half2*)&v1.x); vb = __half22float2(*(__half2*)&v1.y);
        ax += e1 * va.x; ay += e1 * va.y; az += e1 * vb.x; aw += e1 * vb.y;
        va = __half22float2(*(__half2*)&v2.x); vb = __half22float2(*(__half2*)&v2.y);
        ax += e2 * va.x; ay += e2 * va.y; az += e2 * vb.x; aw += e2 * vb.y;
        va = __half22float2(*(__half2*)&v3.x); vb = __half22float2(*(__half2*)&v3.y);
        ax += e3 * va.x; ay += e3 * va.y; az += e3 * vb.x; aw += e3 * vb.y;
    }
    for (; j < end; j++) {
        int d = g_edge_dst[j];
        uint2 ku = K2[(size_t)d * 32 + lane];
        uint2 vu = V2[(size_t)d * 32 + lane];
        float p = dot_kh(q, ku);
        p += __shfl_xor_sync(0xffffffffu, p, 1);
        p += __shfl_xor_sync(0xffffffffu, p, 2);
        p += __shfl_xor_sync(0xffffffffu, p, 4);
        float e = __expf(p * sc);
        z += e;
        float2 va = __half22float2(*(__half2*)&vu.x);
        float2 vb = __half22float2(*(__half2*)&vu.y);
        ax += e * va.x; ay += e * va.y; az += e * vb.x; aw += e * vb.y;
    }
    float inv = (z > 0.0f) ? (1.0f / z) : 0.0f;
    float4 o;
    o.x = ax * inv; o.y = ay * inv; o.z = az * inv; o.w = aw * inv;
    ((float4*)g_attn)[(size_t)n * 32 + lane] = o;
}

// ---------------- launch ----------------
extern "C" void kernel_launch(void* const* d_in, const int* in_sizes, int n_in,
                              void* d_out, int out_size)
{
    const float* x_node = (const float*)d_in[0];
    const float* x_edge = (const float*)d_in[1];
    const int*   src    = (const int*)d_in[2];
    const int*   dst    = (const int*)d_in[3];
    const float* Wq     = (const float*)d_in[4];
    const float* bq     = (const float*)d_in[5];
    const float* Wk     = (const float*)d_in[6];
    const float* bk     = (const float*)d_in[7];
    const float* Wv     = (const float*)d_in[8];
    const float* bv     = (const float*)d_in[9];
    const float* Wo     = (const float*)d_in[10];
    const float* bo     = (const float*)d_in[11];
    float* out = (float*)d_out;

    int NN = in_sizes[0] / 128;
    int ME = in_sizes[1] / 128;
    int E  = in_sizes[2];

    float *Qp, *Ap;
    __half *Khp, *Vhp;
    uint4* Wspp;
    cudaGetSymbolAddress((void**)&Qp, g_Q);
    cudaGetSymbolAddress((void**)&Khp, g_Kh);
    cudaGetSymbolAddress((void**)&Vhp, g_Vh);
    cudaGetSymbolAddress((void**)&Ap, g_attn);
    cudaGetSymbolAddress((void**)&Wspp, g_Wsp);
    const int wstride = (int)((size_t)2 * 128 * 136 * sizeof(__half) / sizeof(uint4));  // 4352

    cudaFuncSetAttribute(k_mega,  cudaFuncAttributeMaxDynamicSharedMemorySize, GEMM_SMEM);
    cudaFuncSetAttribute(k_gemmO, cudaFuncAttributeMaxDynamicSharedMemorySize, GEMM_SMEM);

    int gq = (NN + 63) / 64;   // 782
    int ge = (ME + 63) / 64;   // 313
    int megaBlocks = SCAT_BLKS + gq + 2 * ge;

    k_prep<<<256 + HIST_BLKS, 256>>>(Wq, Wk, Wv, Wo, src, E);
    k_scan<<<1, 1024>>>(NN);
    k_mega<<<megaBlocks, 256, GEMM_SMEM>>>(x_node, x_edge, src, dst, Wspp,
                                           bq, bk, bv, Qp, Khp, Vhp,
                                           NN, ME, E, gq, ge, wstride);
    k_attn<<<(NN + 7) / 8, 256>>>(NN);
    k_gemmO<<<gq, 256, GEMM_SMEM>>>(Ap, Wspp + 3 * (size_t)wstride, bo, x_node, out, NN);
}